// round 8
// baseline (speedup 1.0000x reference)
#include <cuda_runtime.h>

#define Bc 8
#define Cc 96
#define Hc 256
#define Wc 256
#define TH 8
#define RROWS 16               // raw rows: img rowBase-4 .. rowBase+11 (slot = imgrow-rowBase+4)
#define VRS 10                 // vsum/bp rows: img rowBase-1 .. rowBase+8 (vr = g-rowBase+1)
#define NQ 66
#define QS 67

typedef unsigned long long ull;
#define NEG1X2 0xBF800000BF800000ull   // (-1.0f, -1.0f)

__device__ __forceinline__ ull add2(ull a, ull b) {
    ull r; asm("add.rn.f32x2 %0,%1,%2;" : "=l"(r) : "l"(a), "l"(b)); return r;
}
__device__ __forceinline__ ull fma2(ull a, ull b, ull c) {
    ull r; asm("fma.rn.f32x2 %0,%1,%2,%3;" : "=l"(r) : "l"(a), "l"(b), "l"(c)); return r;
}
// c - a
__device__ __forceinline__ ull sub2r(ull a, ull c) { return fma2(a, NEG1X2, c); }

// reciprocal of valid-count for avgpool (count_include_pad=False); 0 outside image
__device__ __forceinline__ float rcnt0(int i, int p) {
    if (i < 0 || i > Hc - 1) return 0.f;
    int lo = i - p; if (lo < 0) lo = 0;
    int hi = i + p; if (hi > Hc - 1) hi = Hc - 1;
    return __fdividef(1.f, (float)(hi - lo + 1));
}

__device__ __forceinline__ float bn_silu(float acc, float scal, float shft) {
    float v = fmaf(acc, scal, shft);
    return v * __fdividef(1.f, 1.f + __expf(-v));
}

// 3 consecutive quads -> 12 floats (img cols 4j-4 .. 4j+7 when base = buf + vr*QS + j)
__device__ __forceinline__ void ld12(const float4* __restrict__ p, float* __restrict__ d) {
    float4 A = p[0], B = p[1], C = p[2];
    d[0]=A.x; d[1]=A.y; d[2]=A.z;  d[3]=A.w;
    d[4]=B.x; d[5]=B.y; d[6]=B.z;  d[7]=B.w;
    d[8]=C.x; d[9]=C.y; d[10]=C.z; d[11]=C.w;
}

__global__ __launch_bounds__(256, 5) void trifreq_kernel(
    const float* __restrict__ x,
    const float* __restrict__ w_lo,
    const float* __restrict__ w_mf,
    const float* __restrict__ w_hf,
    const float* __restrict__ bn_gamma,
    const float* __restrict__ bn_beta,
    const float* __restrict__ bn_mean,
    const float* __restrict__ bn_var,
    float* __restrict__ out)
{
    __shared__ float4 s_raw[RROWS * QS];
    __shared__ float4 s_v3[VRS * QS];    // vertical 3-sums
    __shared__ float4 s_v7[VRS * QS];    // vertical 7-sums (mf only)
    __shared__ float s_w[25];

    const int t = threadIdx.x;
    const int tileY = blockIdx.x;
    const int ch = blockIdx.y;
    const int b = blockIdx.z;
    const int group = ch >> 5;
    const int k = ch & 31;
    const int rowBase = tileY * TH;

    if (group == 0)      { if (t < 25) s_w[t] = w_lo[k * 25 + t]; }
    else if (group == 1) { if (t < 9)  s_w[t] = w_mf[k * 9 + t]; }
    else                 { if (t < 9)  s_w[t] = w_hf[k * 9 + t]; }

    // ---- raw tile load, division-free: 16 thread-groups of 16, one row each ----
    const float* xp = x + (size_t)(b * Cc + ch) * Hc * Wc;
    const int rlo = (group == 0) ? 2 : 0;
    const int rhi = (group == 0) ? 14 : 16;
    {
        int rr = rlo + (t >> 4);
        if (rr < rhi) {
            int gr = rowBase + rr - 4;
            bool rowOK = (unsigned)gr < (unsigned)Hc;
            const float* rowp = xp + gr * Wc;
            float4* srow = s_raw + rr * QS;
            for (int qq = (t & 15); qq < NQ; qq += 16) {
                float4 v = make_float4(0.f, 0.f, 0.f, 0.f);
                if (qq >= 1 && qq <= 64 && rowOK)
                    v = *(const float4*)(rowp + (qq - 1) * 4);
                srow[qq] = v;
            }
        }
    }
    __syncthreads();

    const int oc = 3 * k + group;                 // channel shuffle folded in
    const float inv  = bn_gamma[oc] * rsqrtf(bn_var[oc] + 1e-5f);
    const float shft = bn_beta[oc] - bn_mean[oc] * inv;

    const int j = t & 63;                         // quad: output cols 4j..4j+3
    const int rc = t >> 6;                        // 2-row band
    const int gy0 = rowBase + 2 * rc;             // output rows gy0, gy0+1
    float* outp = out + (size_t)(b * Cc + oc) * Hc * Wc + j * 4;

    if (group == 0) {
        // ===== lo: 5x5 dwconv, single-pass scatter over 6 raw rows, weights in regs =====
        float w[25];
#pragma unroll
        for (int i = 0; i < 25; i++) w[i] = s_w[i];
        float a0[4] = {0.f,0.f,0.f,0.f}, a1[4] = {0.f,0.f,0.f,0.f};
#pragma unroll
        for (int rrow = 0; rrow < 6; rrow++) {
            float u[12];
            ld12(s_raw + (2 * rc + 2 + rrow) * QS + j, u);   // img row gy0-2+rrow
            if (rrow < 5) {
#pragma unroll
                for (int kc = 0; kc < 5; kc++) {
                    float wv = w[rrow * 5 + kc];
#pragma unroll
                    for (int p = 0; p < 4; p++) a0[p] = fmaf(wv, u[p + kc + 2], a0[p]);
                }
            }
            if (rrow >= 1) {
#pragma unroll
                for (int kc = 0; kc < 5; kc++) {
                    float wv = w[(rrow - 1) * 5 + kc];
#pragma unroll
                    for (int p = 0; p < 4; p++) a1[p] = fmaf(wv, u[p + kc + 2], a1[p]);
                }
            }
        }
        float4 o;
        o.x = bn_silu(a0[0], inv, shft); o.y = bn_silu(a0[1], inv, shft);
        o.z = bn_silu(a0[2], inv, shft); o.w = bn_silu(a0[3], inv, shft);
        *(float4*)(outp + (size_t)gy0 * Wc) = o;
        o.x = bn_silu(a1[0], inv, shft); o.y = bn_silu(a1[1], inv, shft);
        o.z = bn_silu(a1[2], inv, shft); o.w = bn_silu(a1[3], inv, shft);
        *(float4*)(outp + (size_t)(gy0 + 1) * Wc) = o;
        return;
    }

    float icx3[6];
#pragma unroll
    for (int m = 0; m < 6; m++) icx3[m] = rcnt0(4 * j - 1 + m, 1);

    if (group == 1) {
        // ===== mf: vertical 3/7 sums, packed f32x2 (chunks of 2 rows) =====
        for (int idx = t; idx < 5 * NQ; idx += 256) {
            int chunk = idx / NQ;
            int qq = idx - chunk * NQ;
            int vr0 = chunk * 2;
            const ulonglong2* col = (const ulonglong2*)s_raw + qq;
            ulonglong2 r0 = col[(vr0+0)*QS], r1 = col[(vr0+1)*QS], r2 = col[(vr0+2)*QS],
                       r3 = col[(vr0+3)*QS], r4 = col[(vr0+4)*QS], r5 = col[(vr0+5)*QS],
                       r6 = col[(vr0+6)*QS], r7 = col[(vr0+7)*QS];
            ulonglong2 s3, s7;
            s3.x = add2(add2(r2.x, r3.x), r4.x);
            s3.y = add2(add2(r2.y, r3.y), r4.y);
            s7.x = add2(add2(add2(r0.x, r1.x), add2(r5.x, r6.x)), s3.x);
            s7.y = add2(add2(add2(r0.y, r1.y), add2(r5.y, r6.y)), s3.y);
            ((ulonglong2*)s_v3)[vr0 * QS + qq] = s3;
            ((ulonglong2*)s_v7)[vr0 * QS + qq] = s7;
            s3.x = add2(s3.x, sub2r(r2.x, r5.x));   // += r5 - r2
            s3.y = add2(s3.y, sub2r(r2.y, r5.y));
            s7.x = add2(s7.x, sub2r(r0.x, r7.x));   // += r7 - r0
            s7.y = add2(s7.y, sub2r(r0.y, r7.y));
            ((ulonglong2*)s_v3)[(vr0 + 1) * QS + qq] = s3;
            ((ulonglong2*)s_v7)[(vr0 + 1) * QS + qq] = s7;
        }
        __syncthreads();

        // ===== fused band-pass + 3x3 conv scatter, weights in regs =====
        float w[9];
#pragma unroll
        for (int i = 0; i < 9; i++) w[i] = s_w[i];
        float icx7[6];
#pragma unroll
        for (int m = 0; m < 6; m++) icx7[m] = rcnt0(4 * j - 1 + m, 3);
        float a0[4] = {0.f,0.f,0.f,0.f}, a1[4] = {0.f,0.f,0.f,0.f};
#pragma unroll
        for (int rrow = 0; rrow < 4; rrow++) {
            int vr = 2 * rc + rrow;               // bp row g = gy0-1+rrow
            int g = gy0 - 1 + rrow;
            float iy3 = rcnt0(g, 1), iy7 = rcnt0(g, 3);
            float bp[6];
            {
                float u[12];
                ld12(s_v3 + vr * QS + j, u);      // v3 cols 4j-4..4j+7
                float h = u[2] + u[3] + u[4];     // h3 for bp col 4j-1
                bp[0] = h * (icx3[0] * iy3);
#pragma unroll
                for (int m = 1; m < 6; m++) {
                    h += u[m + 4] - u[m + 1];
                    bp[m] = h * (icx3[m] * iy3);
                }
            }
            {
                float u[12];
                ld12(s_v7 + vr * QS + j, u);      // v7 cols 4j-4..4j+7
                float h = u[0]+u[1]+u[2]+u[3]+u[4]+u[5]+u[6];   // h7 for bp col 4j-1
                bp[0] -= h * (icx7[0] * iy7);
#pragma unroll
                for (int m = 1; m < 6; m++) {
                    h += u[m + 6] - u[m - 1];
                    bp[m] -= h * (icx7[m] * iy7);
                }
            }
            if (rrow < 3) {
#pragma unroll
                for (int kc = 0; kc < 3; kc++) {
                    float wv = w[rrow * 3 + kc];
#pragma unroll
                    for (int p = 0; p < 4; p++) a0[p] = fmaf(wv, bp[p + kc], a0[p]);
                }
            }
            if (rrow >= 1) {
#pragma unroll
                for (int kc = 0; kc < 3; kc++) {
                    float wv = w[(rrow - 1) * 3 + kc];
#pragma unroll
                    for (int p = 0; p < 4; p++) a1[p] = fmaf(wv, bp[p + kc], a1[p]);
                }
            }
        }
        float4 o;
        o.x = bn_silu(a0[0], inv, shft); o.y = bn_silu(a0[1], inv, shft);
        o.z = bn_silu(a0[2], inv, shft); o.w = bn_silu(a0[3], inv, shft);
        *(float4*)(outp + (size_t)gy0 * Wc) = o;
        o.x = bn_silu(a1[0], inv, shft); o.y = bn_silu(a1[1], inv, shft);
        o.z = bn_silu(a1[2], inv, shft); o.w = bn_silu(a1[3], inv, shft);
        *(float4*)(outp + (size_t)(gy0 + 1) * Wc) = o;
        return;
    }

    // ===== hf: vertical 3-sums, packed f32x2 (chunks of 2 rows) =====
    for (int idx = t; idx < 5 * NQ; idx += 256) {
        int chunk = idx / NQ;
        int qq = idx - chunk * NQ;
        int vr0 = chunk * 2;
        const ulonglong2* col = (const ulonglong2*)s_raw + qq;
        ulonglong2 r2 = col[(vr0+2)*QS], r3 = col[(vr0+3)*QS],
                   r4 = col[(vr0+4)*QS], r5 = col[(vr0+5)*QS];
        ulonglong2 s3;
        s3.x = add2(add2(r2.x, r3.x), r4.x);
        s3.y = add2(add2(r2.y, r3.y), r4.y);
        ((ulonglong2*)s_v3)[vr0 * QS + qq] = s3;
        s3.x = add2(s3.x, sub2r(r2.x, r5.x));
        s3.y = add2(s3.y, sub2r(r2.y, r5.y));
        ((ulonglong2*)s_v3)[(vr0 + 1) * QS + qq] = s3;
    }
    __syncthreads();

    // ===== fused high-pass + 3x3 conv scatter, weights in regs =====
    {
        float w[9];
#pragma unroll
        for (int i = 0; i < 9; i++) w[i] = s_w[i];
        float a0[4] = {0.f,0.f,0.f,0.f}, a1[4] = {0.f,0.f,0.f,0.f};
#pragma unroll
        for (int rrow = 0; rrow < 4; rrow++) {
            int vr = 2 * rc + rrow;               // hp row g = gy0-1+rrow
            int g = gy0 - 1 + rrow;
            float iy3 = rcnt0(g, 1);
            float hp[6];
            {
                float u[12], ur[12];
                ld12(s_v3 + vr * QS + j, u);              // v3 cols 4j-4..4j+7
                ld12(s_raw + (vr + 3) * QS + j, ur);      // raw row g, cols 4j-4..4j+7
                float h = u[2] + u[3] + u[4];             // h3 for col 4j-1
                hp[0] = ur[3] - h * (icx3[0] * iy3);
#pragma unroll
                for (int m = 1; m < 6; m++) {
                    h += u[m + 4] - u[m + 1];
                    hp[m] = ur[m + 3] - h * (icx3[m] * iy3);
                }
            }
            if (rrow < 3) {
#pragma unroll
                for (int kc = 0; kc < 3; kc++) {
                    float wv = w[rrow * 3 + kc];
#pragma unroll
                    for (int p = 0; p < 4; p++) a0[p] = fmaf(wv, hp[p + kc], a0[p]);
                }
            }
            if (rrow >= 1) {
#pragma unroll
                for (int kc = 0; kc < 3; kc++) {
                    float wv = w[(rrow - 1) * 3 + kc];
#pragma unroll
                    for (int p = 0; p < 4; p++) a1[p] = fmaf(wv, hp[p + kc], a1[p]);
                }
            }
        }
        float4 o;
        o.x = bn_silu(a0[0], inv, shft); o.y = bn_silu(a0[1], inv, shft);
        o.z = bn_silu(a0[2], inv, shft); o.w = bn_silu(a0[3], inv, shft);
        *(float4*)(outp + (size_t)gy0 * Wc) = o;
        o.x = bn_silu(a1[0], inv, shft); o.y = bn_silu(a1[1], inv, shft);
        o.z = bn_silu(a1[2], inv, shft); o.w = bn_silu(a1[3], inv, shft);
        *(float4*)(outp + (size_t)(gy0 + 1) * Wc) = o;
    }
}

extern "C" void kernel_launch(void* const* d_in, const int* in_sizes, int n_in,
                              void* d_out, int out_size) {
    (void)in_sizes; (void)n_in; (void)out_size;
    dim3 grid(Hc / TH, Cc, Bc);
    dim3 block(256);
    trifreq_kernel<<<grid, block>>>(
        (const float*)d_in[0], (const float*)d_in[1], (const float*)d_in[2],
        (const float*)d_in[3], (const float*)d_in[4], (const float*)d_in[5],
        (const float*)d_in[6], (const float*)d_in[7], (float*)d_out);
}

// round 10
// speedup vs baseline: 1.0135x; 1.0135x over previous
#include <cuda_runtime.h>

#define Bc 8
#define Cc 96
#define Hc 256
#define Wc 256
#define TH 8
#define RROWS 16               // raw rows: img rowBase-4 .. rowBase+11 (slot = imgrow-rowBase+4)
#define VRS 10                 // vsum/bp rows: img rowBase-1 .. rowBase+8 (vr = g-rowBase+1)
#define NQ 66
#define QS 67

typedef unsigned long long ull;
#define NEG1X2 0xBF800000BF800000ull   // (-1.0f, -1.0f)

__device__ __forceinline__ ull add2(ull a, ull b) {
    ull r; asm("add.rn.f32x2 %0,%1,%2;" : "=l"(r) : "l"(a), "l"(b)); return r;
}
__device__ __forceinline__ ull fma2(ull a, ull b, ull c) {
    ull r; asm("fma.rn.f32x2 %0,%1,%2,%3;" : "=l"(r) : "l"(a), "l"(b), "l"(c)); return r;
}
__device__ __forceinline__ ull sub2r(ull a, ull c) { return fma2(a, NEG1X2, c); }  // c - a

// reciprocal of valid-count for avgpool (count_include_pad=False); 0 outside image
__device__ __forceinline__ float rcnt0(int i, int p) {
    if (i < 0 || i > Hc - 1) return 0.f;
    int lo = i - p; if (lo < 0) lo = 0;
    int hi = i + p; if (hi > Hc - 1) hi = Hc - 1;
    return __fdividef(1.f, (float)(hi - lo + 1));
}

__device__ __forceinline__ float bn_silu(float acc, float scal, float shft) {
    float v = fmaf(acc, scal, shft);
    return v * __fdividef(1.f, 1.f + __expf(-v));
}

// 2 consecutive quads -> 8 floats
__device__ __forceinline__ void ld8(const float4* __restrict__ p, float* __restrict__ d) {
    float4 A = p[0], B = p[1];
    d[0]=A.x; d[1]=A.y; d[2]=A.z; d[3]=A.w;
    d[4]=B.x; d[5]=B.y; d[6]=B.z; d[7]=B.w;
}
// 3 consecutive quads -> 12 floats
__device__ __forceinline__ void ld12(const float4* __restrict__ p, float* __restrict__ d) {
    float4 A = p[0], B = p[1], C = p[2];
    d[0]=A.x; d[1]=A.y; d[2]=A.z;  d[3]=A.w;
    d[4]=B.x; d[5]=B.y; d[6]=B.z;  d[7]=B.w;
    d[8]=C.x; d[9]=C.y; d[10]=C.z; d[11]=C.w;
}

// 3x3 conv scatter over buffer rows s0..s0+3, outputs 2 rows gy0, gy0+1.
// buf row slots hold cols 4j-4..4j+7 at (slot*QS + j); u[idx] = col 4j-4+idx.
// Output col 4j+p needs cols 4j+p-1..4j+p+1 = u[p+3..p+5]  ->  u[p + kc + 3].
__device__ __forceinline__ void conv3_scatter(const float4* __restrict__ bufj, int s0,
                                              const float* __restrict__ sw,
                                              float inv, float shft,
                                              float* __restrict__ outp, int gy0) {
    float w[9];
#pragma unroll
    for (int i = 0; i < 9; i++) w[i] = sw[i];
    float a0[4] = {0.f,0.f,0.f,0.f}, a1[4] = {0.f,0.f,0.f,0.f};
#pragma unroll
    for (int rrow = 0; rrow < 4; rrow++) {
        float u[12];
        ld12(bufj + (s0 + rrow) * QS, u);
        if (rrow < 3) {
#pragma unroll
            for (int kc = 0; kc < 3; kc++) {
                float wv = w[rrow * 3 + kc];
#pragma unroll
                for (int p = 0; p < 4; p++) a0[p] = fmaf(wv, u[p + kc + 3], a0[p]);
            }
        }
        if (rrow >= 1) {
#pragma unroll
            for (int kc = 0; kc < 3; kc++) {
                float wv = w[(rrow - 1) * 3 + kc];
#pragma unroll
                for (int p = 0; p < 4; p++) a1[p] = fmaf(wv, u[p + kc + 3], a1[p]);
            }
        }
    }
    float4 o;
    o.x = bn_silu(a0[0], inv, shft); o.y = bn_silu(a0[1], inv, shft);
    o.z = bn_silu(a0[2], inv, shft); o.w = bn_silu(a0[3], inv, shft);
    *(float4*)(outp + (size_t)gy0 * Wc) = o;
    o.x = bn_silu(a1[0], inv, shft); o.y = bn_silu(a1[1], inv, shft);
    o.z = bn_silu(a1[2], inv, shft); o.w = bn_silu(a1[3], inv, shft);
    *(float4*)(outp + (size_t)(gy0 + 1) * Wc) = o;
}

__global__ __launch_bounds__(256, 5) void trifreq_kernel(
    const float* __restrict__ x,
    const float* __restrict__ w_lo,
    const float* __restrict__ w_mf,
    const float* __restrict__ w_hf,
    const float* __restrict__ bn_gamma,
    const float* __restrict__ bn_beta,
    const float* __restrict__ bn_mean,
    const float* __restrict__ bn_var,
    float* __restrict__ out)
{
    __shared__ float4 s_raw[RROWS * QS];   // raw; mf reuses rows 0..9 as bp buffer
    __shared__ float4 s_v3[VRS * QS];      // vertical 3-sums
    __shared__ float4 s_v7[VRS * QS];      // mf: vertical 7-sums; hf: hp buffer
    __shared__ float s_w[25];

    const int t = threadIdx.x;
    const int tileY = blockIdx.x;
    const int ch = blockIdx.y;
    const int b = blockIdx.z;
    const int group = ch >> 5;
    const int k = ch & 31;
    const int rowBase = tileY * TH;

    if (group == 0)      { if (t < 25) s_w[t] = w_lo[k * 25 + t]; }
    else if (group == 1) { if (t < 9)  s_w[t] = w_mf[k * 9 + t]; }
    else                 { if (t < 9)  s_w[t] = w_hf[k * 9 + t]; }

    // ---- raw tile load, division-free (16 groups of 16 threads, one row each) ----
    const float* xp = x + (size_t)(b * Cc + ch) * Hc * Wc;
    const int rlo = (group == 0) ? 2 : 0;
    const int rhi = (group == 0) ? 14 : 16;
    {
        int rr = rlo + (t >> 4);
        if (rr < rhi) {
            int gr = rowBase + rr - 4;
            bool rowOK = (unsigned)gr < (unsigned)Hc;
            const float* rowp = xp + gr * Wc;
            float4* srow = s_raw + rr * QS;
            for (int qq = (t & 15); qq < NQ; qq += 16) {
                float4 v = make_float4(0.f, 0.f, 0.f, 0.f);
                if (qq >= 1 && qq <= 64 && rowOK)
                    v = *(const float4*)(rowp + (qq - 1) * 4);
                srow[qq] = v;
            }
        }
    }
    __syncthreads();

    const int oc = 3 * k + group;                 // channel shuffle folded in
    const float inv  = bn_gamma[oc] * rsqrtf(bn_var[oc] + 1e-5f);
    const float shft = bn_beta[oc] - bn_mean[oc] * inv;

    const int j = t & 63;                         // quad: output cols 4j..4j+3
    const int rc = t >> 6;                        // 2-row band for conv / 4-stride for bp
    const int gy0 = rowBase + 2 * rc;
    float* outp = out + (size_t)(b * Cc + oc) * Hc * Wc + j * 4;

    if (group == 0) {
        // ===== lo: 5x5 dwconv, single-pass scatter over 6 raw rows =====
        float w[25];
#pragma unroll
        for (int i = 0; i < 25; i++) w[i] = s_w[i];
        float a0[4] = {0.f,0.f,0.f,0.f}, a1[4] = {0.f,0.f,0.f,0.f};
#pragma unroll
        for (int rrow = 0; rrow < 6; rrow++) {
            float u[12];
            ld12(s_raw + (2 * rc + 2 + rrow) * QS + j, u);   // img row gy0-2+rrow
            if (rrow < 5) {
#pragma unroll
                for (int kc = 0; kc < 5; kc++) {
                    float wv = w[rrow * 5 + kc];
#pragma unroll
                    for (int p = 0; p < 4; p++) a0[p] = fmaf(wv, u[p + kc + 2], a0[p]);
                }
            }
            if (rrow >= 1) {
#pragma unroll
                for (int kc = 0; kc < 5; kc++) {
                    float wv = w[(rrow - 1) * 5 + kc];
#pragma unroll
                    for (int p = 0; p < 4; p++) a1[p] = fmaf(wv, u[p + kc + 2], a1[p]);
                }
            }
        }
        float4 o;
        o.x = bn_silu(a0[0], inv, shft); o.y = bn_silu(a0[1], inv, shft);
        o.z = bn_silu(a0[2], inv, shft); o.w = bn_silu(a0[3], inv, shft);
        *(float4*)(outp + (size_t)gy0 * Wc) = o;
        o.x = bn_silu(a1[0], inv, shft); o.y = bn_silu(a1[1], inv, shft);
        o.z = bn_silu(a1[2], inv, shft); o.w = bn_silu(a1[3], inv, shft);
        *(float4*)(outp + (size_t)(gy0 + 1) * Wc) = o;
        return;
    }

    float icx3[4];
#pragma unroll
    for (int m = 0; m < 4; m++) icx3[m] = rcnt0(4 * j + m, 1);

    if (group == 1) {
        // ===== mf: vertical 3/7 sums (packed f32x2), 2-row chunks =====
        for (int idx = t; idx < 5 * NQ; idx += 256) {
            int chunk = idx / NQ;
            int qq = idx - chunk * NQ;
            int vr0 = chunk * 2;
            const ulonglong2* col = (const ulonglong2*)s_raw + qq;
            ulonglong2 r0 = col[(vr0+0)*QS], r1 = col[(vr0+1)*QS], r2 = col[(vr0+2)*QS],
                       r3 = col[(vr0+3)*QS], r4 = col[(vr0+4)*QS], r5 = col[(vr0+5)*QS],
                       r6 = col[(vr0+6)*QS], r7 = col[(vr0+7)*QS];
            ulonglong2 s3, s7;
            s3.x = add2(add2(r2.x, r3.x), r4.x);
            s3.y = add2(add2(r2.y, r3.y), r4.y);
            s7.x = add2(add2(add2(r0.x, r1.x), add2(r5.x, r6.x)), s3.x);
            s7.y = add2(add2(add2(r0.y, r1.y), add2(r5.y, r6.y)), s3.y);
            ((ulonglong2*)s_v3)[vr0 * QS + qq] = s3;
            ((ulonglong2*)s_v7)[vr0 * QS + qq] = s7;
            s3.x = add2(s3.x, sub2r(r2.x, r5.x));
            s3.y = add2(s3.y, sub2r(r2.y, r5.y));
            s7.x = add2(s7.x, sub2r(r0.x, r7.x));
            s7.y = add2(s7.y, sub2r(r0.y, r7.y));
            ((ulonglong2*)s_v3)[(vr0 + 1) * QS + qq] = s3;
            ((ulonglong2*)s_v7)[(vr0 + 1) * QS + qq] = s7;
        }
        __syncthreads();

        // ===== band-pass computed ONCE, 4-wide, into s_raw rows 0..9 =====
        float icx7[4];
#pragma unroll
        for (int m = 0; m < 4; m++) icx7[m] = rcnt0(4 * j + m, 3);
        for (int vr = rc; vr < VRS; vr += 4) {
            int g = rowBase + vr - 1;
            float iy3 = rcnt0(g, 1), iy7 = rcnt0(g, 3);
            float u3[8], u7[12];
            ld8(s_v3 + vr * QS + j, u3);          // v3 cols 4j-4..4j+3
            ld12(s_v7 + vr * QS + j, u7);         // v7 cols 4j-4..4j+7
            float4 o;
            float h3 = u3[2] + u3[3] + u3[4];     // col 4j-1
            float h7 = u7[0]+u7[1]+u7[2]+u7[3]+u7[4]+u7[5]+u7[6];  // col 4j-1
            h3 += u3[5] - u3[2];  h7 += u7[7] - u7[0];
            o.x = h3 * (icx3[0] * iy3) - h7 * (icx7[0] * iy7);
            h3 += u3[6] - u3[3];  h7 += u7[8] - u7[1];
            o.y = h3 * (icx3[1] * iy3) - h7 * (icx7[1] * iy7);
            h3 += u3[7] - u3[4];  h7 += u7[9] - u7[2];
            o.z = h3 * (icx3[2] * iy3) - h7 * (icx7[2] * iy7);
            h3 += ((const float*)(s_v3 + vr * QS + j + 2))[0] - u3[5];  // col 4j+4
            h7 += u7[10] - u7[3];
            o.w = h3 * (icx3[3] * iy3) - h7 * (icx7[3] * iy7);
            s_raw[vr * QS + j + 1] = o;
        }
        __syncthreads();
        conv3_scatter(s_raw + j, 2 * rc, s_w, inv, shft, outp, gy0);
        return;
    }

    // ===== hf: vertical 3-sums (packed f32x2) =====
    for (int idx = t; idx < 5 * NQ; idx += 256) {
        int chunk = idx / NQ;
        int qq = idx - chunk * NQ;
        int vr0 = chunk * 2;
        const ulonglong2* col = (const ulonglong2*)s_raw + qq;
        ulonglong2 r2 = col[(vr0+2)*QS], r3 = col[(vr0+3)*QS],
                   r4 = col[(vr0+4)*QS], r5 = col[(vr0+5)*QS];
        ulonglong2 s3;
        s3.x = add2(add2(r2.x, r3.x), r4.x);
        s3.y = add2(add2(r2.y, r3.y), r4.y);
        ((ulonglong2*)s_v3)[vr0 * QS + qq] = s3;
        s3.x = add2(s3.x, sub2r(r2.x, r5.x));
        s3.y = add2(s3.y, sub2r(r2.y, r5.y));
        ((ulonglong2*)s_v3)[(vr0 + 1) * QS + qq] = s3;
    }
    // zero hp-buffer (s_v7) edge quads for the conv halo
    if (t < 2 * VRS) {
        int vr = t % VRS;
        int qe = (t < VRS) ? 0 : 65;
        s_v7[vr * QS + qe] = make_float4(0.f, 0.f, 0.f, 0.f);
    }
    __syncthreads();

    // ===== high-pass computed ONCE, 4-wide, into s_v7 rows 0..9 =====
    for (int vr = rc; vr < VRS; vr += 4) {
        int g = rowBase + vr - 1;
        float iy3 = rcnt0(g, 1);
        float u3[12];
        ld12(s_v3 + vr * QS + j, u3);             // v3 cols 4j-4..4j+7
        float4 rawv = s_raw[(vr + 3) * QS + j + 1];   // raw row g, cols 4j..4j+3
        float4 o;
        float h3 = u3[3] + u3[4] + u3[5];         // col 4j
        o.x = rawv.x - h3 * (icx3[0] * iy3);
        h3 += u3[6] - u3[3];
        o.y = rawv.y - h3 * (icx3[1] * iy3);
        h3 += u3[7] - u3[4];
        o.z = rawv.z - h3 * (icx3[2] * iy3);
        h3 += u3[8] - u3[5];
        o.w = rawv.w - h3 * (icx3[3] * iy3);
        s_v7[vr * QS + j + 1] = o;
    }
    __syncthreads();
    conv3_scatter(s_v7 + j, 2 * rc, s_w, inv, shft, outp, gy0);
}

extern "C" void kernel_launch(void* const* d_in, const int* in_sizes, int n_in,
                              void* d_out, int out_size) {
    (void)in_sizes; (void)n_in; (void)out_size;
    dim3 grid(Hc / TH, Cc, Bc);
    dim3 block(256);
    trifreq_kernel<<<grid, block>>>(
        (const float*)d_in[0], (const float*)d_in[1], (const float*)d_in[2],
        (const float*)d_in[3], (const float*)d_in[4], (const float*)d_in[5],
        (const float*)d_in[6], (const float*)d_in[7], (float*)d_out);
}

// round 11
// speedup vs baseline: 1.2183x; 1.2020x over previous
#include <cuda_runtime.h>

#define Bc 8
#define Cc 96
#define Hc 256
#define Wc 256
#define TH 8
#define RROWS 16               // raw rows: img rowBase-4 .. rowBase+11 (slot = imgrow-rowBase+4)
#define VRS 10                 // vsum/bp rows: img rowBase-1 .. rowBase+8 (vr = g-rowBase+1)
#define NQ 66
#define QS 67
#define RWF (QS * 4)           // floats per smem row (268)
#define NU 264                 // column units: col c = u - 4, c in -4..259

// reciprocal of valid-count for avgpool (count_include_pad=False); 0 outside image
__device__ __forceinline__ float rcnt0(int i, int p) {
    if (i < 0 || i > Hc - 1) return 0.f;
    int lo = i - p; if (lo < 0) lo = 0;
    int hi = i + p; if (hi > Hc - 1) hi = Hc - 1;
    return __fdividef(1.f, (float)(hi - lo + 1));
}

__device__ __forceinline__ float bn_silu(float acc, float scal, float shft) {
    float v = fmaf(acc, scal, shft);
    return v * __fdividef(1.f, 1.f + __expf(-v));
}

// 2 consecutive quads -> 8 floats
__device__ __forceinline__ void ld8(const float4* __restrict__ p, float* __restrict__ d) {
    float4 A = p[0], B = p[1];
    d[0]=A.x; d[1]=A.y; d[2]=A.z; d[3]=A.w;
    d[4]=B.x; d[5]=B.y; d[6]=B.z; d[7]=B.w;
}
// 3 consecutive quads -> 12 floats
__device__ __forceinline__ void ld12(const float4* __restrict__ p, float* __restrict__ d) {
    float4 A = p[0], B = p[1], C = p[2];
    d[0]=A.x; d[1]=A.y; d[2]=A.z;  d[3]=A.w;
    d[4]=B.x; d[5]=B.y; d[6]=B.z;  d[7]=B.w;
    d[8]=C.x; d[9]=C.y; d[10]=C.z; d[11]=C.w;
}

// 3x3 conv scatter over buffer rows s0..s0+3, outputs 2 rows gy0, gy0+1.
// buf row slots hold cols 4j-4..4j+7 at (slot*QS + j); u[idx] = col 4j-4+idx.
// Output col 4j+p needs cols 4j+p-1..4j+p+1 -> u[p + kc + 3].
__device__ __forceinline__ void conv3_scatter(const float4* __restrict__ bufj, int s0,
                                              const float* __restrict__ sw,
                                              float inv, float shft,
                                              float* __restrict__ outp, int gy0) {
    float w[9];
#pragma unroll
    for (int i = 0; i < 9; i++) w[i] = sw[i];
    float a0[4] = {0.f,0.f,0.f,0.f}, a1[4] = {0.f,0.f,0.f,0.f};
#pragma unroll
    for (int rrow = 0; rrow < 4; rrow++) {
        float u[12];
        ld12(bufj + (s0 + rrow) * QS, u);
        if (rrow < 3) {
#pragma unroll
            for (int kc = 0; kc < 3; kc++) {
                float wv = w[rrow * 3 + kc];
#pragma unroll
                for (int p = 0; p < 4; p++) a0[p] = fmaf(wv, u[p + kc + 3], a0[p]);
            }
        }
        if (rrow >= 1) {
#pragma unroll
            for (int kc = 0; kc < 3; kc++) {
                float wv = w[(rrow - 1) * 3 + kc];
#pragma unroll
                for (int p = 0; p < 4; p++) a1[p] = fmaf(wv, u[p + kc + 3], a1[p]);
            }
        }
    }
    float4 o;
    o.x = bn_silu(a0[0], inv, shft); o.y = bn_silu(a0[1], inv, shft);
    o.z = bn_silu(a0[2], inv, shft); o.w = bn_silu(a0[3], inv, shft);
    *(float4*)(outp + (size_t)gy0 * Wc) = o;
    o.x = bn_silu(a1[0], inv, shft); o.y = bn_silu(a1[1], inv, shft);
    o.z = bn_silu(a1[2], inv, shft); o.w = bn_silu(a1[3], inv, shft);
    *(float4*)(outp + (size_t)(gy0 + 1) * Wc) = o;
}

__global__ __launch_bounds__(256, 5) void trifreq_kernel(
    const float* __restrict__ x,
    const float* __restrict__ w_lo,
    const float* __restrict__ w_mf,
    const float* __restrict__ w_hf,
    const float* __restrict__ bn_gamma,
    const float* __restrict__ bn_beta,
    const float* __restrict__ bn_mean,
    const float* __restrict__ bn_var,
    float* __restrict__ out)
{
    __shared__ float4 s_raw[RROWS * QS];   // lo: raw tile; mf: bp buffer rows 0..9; hf: raw rows 3..12
    __shared__ float4 s_v3[VRS * QS];      // vertical 3-sums
    __shared__ float4 s_v7[VRS * QS];      // mf: vertical 7-sums; hf: hp buffer
    __shared__ float s_w[25];

    const int t = threadIdx.x;
    const int tileY = blockIdx.x;
    const int ch = blockIdx.y;
    const int b = blockIdx.z;
    const int group = ch >> 5;
    const int k = ch & 31;
    const int rowBase = tileY * TH;

    if (group == 0)      { if (t < 25) s_w[t] = w_lo[k * 25 + t]; }
    else if (group == 1) { if (t < 9)  s_w[t] = w_mf[k * 9 + t]; }
    else                 { if (t < 9)  s_w[t] = w_hf[k * 9 + t]; }

    const float* xp = x + (size_t)(b * Cc + ch) * Hc * Wc;

    // img row for slot s is rowBase + s - 4
#define LDR(slot) ((colOK && (unsigned)(rowBase + (slot) - 4) < (unsigned)Hc) \
                   ? colp[(size_t)(rowBase + (slot) - 4) * Wc] : 0.f)

    if (group == 0) {
        // ---- lo load: raw slots 2..13 as float4 quads ----
        int rr = 2 + (t >> 4);
        if (rr < 14) {
            int gr = rowBase + rr - 4;
            bool rowOK = (unsigned)gr < (unsigned)Hc;
            const float* rowp = xp + gr * Wc;
            float4* srow = s_raw + rr * QS;
            for (int qq = (t & 15); qq < NQ; qq += 16) {
                float4 v = make_float4(0.f, 0.f, 0.f, 0.f);
                if (qq >= 1 && qq <= 64 && rowOK)
                    v = *(const float4*)(rowp + (qq - 1) * 4);
                srow[qq] = v;
            }
        }
    } else if (group == 1) {
        // ---- mf load-walk: column units, fused v3/v7, no raw staging ----
        float* v3f = (float*)s_v3;
        float* v7f = (float*)s_v7;
        for (int u = t; u < NU; u += 256) {
            int c = u - 4;
            bool colOK = (unsigned)c < (unsigned)Wc;
            const float* colp = xp + c;
            float r[7];
#pragma unroll
            for (int s = 0; s < 7; s++) r[s] = LDR(s);
            float s3 = r[2] + r[3] + r[4];
            float s7 = r[0]+r[1]+r[2]+r[3]+r[4]+r[5]+r[6];
            v3f[u] = s3; v7f[u] = s7;
#pragma unroll
            for (int vr = 1; vr <= 9; vr++) {
                float newv = LDR(vr + 6);
                s3 += r[(vr + 4) % 7] - r[(vr + 1) % 7];
                s7 += newv - r[(vr - 1) % 7];
                r[(vr - 1) % 7] = newv;
                v3f[vr * RWF + u] = s3;
                v7f[vr * RWF + u] = s7;
            }
        }
        // zero bp-buffer edge quads (s_raw rows 0..9, quads 0 & 65)
        if (t < 2 * VRS) {
            int vr = t % VRS;
            int qe = (t < VRS) ? 0 : 65;
            s_raw[vr * QS + qe] = make_float4(0.f, 0.f, 0.f, 0.f);
        }
    } else {
        // ---- hf load-walk: column units, raw slots 3..12 + fused v3 ----
        float* rawf = (float*)s_raw;
        float* v3f = (float*)s_v3;
        for (int u = t; u < NU; u += 256) {
            int c = u - 4;
            bool colOK = (unsigned)c < (unsigned)Wc;
            const float* colp = xp + c;
            float a = LDR(2), bb = LDR(3), cc;
            rawf[3 * RWF + u] = bb;
#pragma unroll
            for (int vr = 0; vr <= 9; vr++) {
                cc = LDR(vr + 4);
                if (vr <= 8) rawf[(vr + 4) * RWF + u] = cc;   // raw slots 4..12
                v3f[vr * RWF + u] = a + bb + cc;              // slots vr+2..vr+4
                a = bb; bb = cc;
            }
        }
        // zero hp-buffer (s_v7) edge quads for the conv halo
        if (t < 2 * VRS) {
            int vr = t % VRS;
            int qe = (t < VRS) ? 0 : 65;
            s_v7[vr * QS + qe] = make_float4(0.f, 0.f, 0.f, 0.f);
        }
    }
    __syncthreads();

    const int oc = 3 * k + group;                 // channel shuffle folded in
    const float inv  = bn_gamma[oc] * rsqrtf(bn_var[oc] + 1e-5f);
    const float shft = bn_beta[oc] - bn_mean[oc] * inv;

    const int j = t & 63;                         // quad: output cols 4j..4j+3
    const int rc = t >> 6;                        // 2-row band / 4-stride for bp
    const int gy0 = rowBase + 2 * rc;
    float* outp = out + (size_t)(b * Cc + oc) * Hc * Wc + j * 4;

    if (group == 0) {
        // ===== lo: 5x5 dwconv, single-pass scatter over 6 raw rows =====
        float w[25];
#pragma unroll
        for (int i = 0; i < 25; i++) w[i] = s_w[i];
        float a0[4] = {0.f,0.f,0.f,0.f}, a1[4] = {0.f,0.f,0.f,0.f};
#pragma unroll
        for (int rrow = 0; rrow < 6; rrow++) {
            float u[12];
            ld12(s_raw + (2 * rc + 2 + rrow) * QS + j, u);   // img row gy0-2+rrow
            if (rrow < 5) {
#pragma unroll
                for (int kc = 0; kc < 5; kc++) {
                    float wv = w[rrow * 5 + kc];
#pragma unroll
                    for (int p = 0; p < 4; p++) a0[p] = fmaf(wv, u[p + kc + 2], a0[p]);
                }
            }
            if (rrow >= 1) {
#pragma unroll
                for (int kc = 0; kc < 5; kc++) {
                    float wv = w[(rrow - 1) * 5 + kc];
#pragma unroll
                    for (int p = 0; p < 4; p++) a1[p] = fmaf(wv, u[p + kc + 2], a1[p]);
                }
            }
        }
        float4 o;
        o.x = bn_silu(a0[0], inv, shft); o.y = bn_silu(a0[1], inv, shft);
        o.z = bn_silu(a0[2], inv, shft); o.w = bn_silu(a0[3], inv, shft);
        *(float4*)(outp + (size_t)gy0 * Wc) = o;
        o.x = bn_silu(a1[0], inv, shft); o.y = bn_silu(a1[1], inv, shft);
        o.z = bn_silu(a1[2], inv, shft); o.w = bn_silu(a1[3], inv, shft);
        *(float4*)(outp + (size_t)(gy0 + 1) * Wc) = o;
        return;
    }

    float icx3[4];
#pragma unroll
    for (int m = 0; m < 4; m++) icx3[m] = rcnt0(4 * j + m, 1);

    if (group == 1) {
        // ===== band-pass computed ONCE, 4-wide, into s_raw rows 0..9 =====
        float icx7[4];
#pragma unroll
        for (int m = 0; m < 4; m++) icx7[m] = rcnt0(4 * j + m, 3);
        for (int vr = rc; vr < VRS; vr += 4) {
            int g = rowBase + vr - 1;
            float iy3 = rcnt0(g, 1), iy7 = rcnt0(g, 3);
            float u3[8], u7[12];
            ld8(s_v3 + vr * QS + j, u3);          // v3 cols 4j-4..4j+3
            ld12(s_v7 + vr * QS + j, u7);         // v7 cols 4j-4..4j+7
            float4 o;
            float h3 = u3[2] + u3[3] + u3[4];     // col 4j-1
            float h7 = u7[0]+u7[1]+u7[2]+u7[3]+u7[4]+u7[5]+u7[6];  // col 4j-1
            h3 += u3[5] - u3[2];  h7 += u7[7] - u7[0];
            o.x = h3 * (icx3[0] * iy3) - h7 * (icx7[0] * iy7);
            h3 += u3[6] - u3[3];  h7 += u7[8] - u7[1];
            o.y = h3 * (icx3[1] * iy3) - h7 * (icx7[1] * iy7);
            h3 += u3[7] - u3[4];  h7 += u7[9] - u7[2];
            o.z = h3 * (icx3[2] * iy3) - h7 * (icx7[2] * iy7);
            h3 += ((const float*)(s_v3 + vr * QS + j + 2))[0] - u3[5];  // col 4j+4
            h7 += u7[10] - u7[3];
            o.w = h3 * (icx3[3] * iy3) - h7 * (icx7[3] * iy7);
            s_raw[vr * QS + j + 1] = o;
        }
        __syncthreads();
        conv3_scatter(s_raw + j, 2 * rc, s_w, inv, shft, outp, gy0);
        return;
    }

    // ===== high-pass computed ONCE, 4-wide, into s_v7 rows 0..9 =====
    for (int vr = rc; vr < VRS; vr += 4) {
        int g = rowBase + vr - 1;
        float iy3 = rcnt0(g, 1);
        float u3[12];
        ld12(s_v3 + vr * QS + j, u3);             // v3 cols 4j-4..4j+7
        float4 rawv = s_raw[(vr + 3) * QS + j + 1];   // raw row g, cols 4j..4j+3
        float4 o;
        float h3 = u3[3] + u3[4] + u3[5];         // col 4j
        o.x = rawv.x - h3 * (icx3[0] * iy3);
        h3 += u3[6] - u3[3];
        o.y = rawv.y - h3 * (icx3[1] * iy3);
        h3 += u3[7] - u3[4];
        o.z = rawv.z - h3 * (icx3[2] * iy3);
        h3 += u3[8] - u3[5];
        o.w = rawv.w - h3 * (icx3[3] * iy3);
        s_v7[vr * QS + j + 1] = o;
    }
    __syncthreads();
    conv3_scatter(s_v7 + j, 2 * rc, s_w, inv, shft, outp, gy0);
}

extern "C" void kernel_launch(void* const* d_in, const int* in_sizes, int n_in,
                              void* d_out, int out_size) {
    (void)in_sizes; (void)n_in; (void)out_size;
    dim3 grid(Hc / TH, Cc, Bc);
    dim3 block(256);
    trifreq_kernel<<<grid, block>>>(
        (const float*)d_in[0], (const float*)d_in[1], (const float*)d_in[2],
        (const float*)d_in[3], (const float*)d_in[4], (const float*)d_in[5],
        (const float*)d_in[6], (const float*)d_in[7], (float*)d_out);
}

// round 12
// speedup vs baseline: 1.2354x; 1.0141x over previous
#include <cuda_runtime.h>

#define Bc 8
#define Cc 96
#define Hc 256
#define Wc 256
#define TH 8
#define VRS 10                 // bp/hp/vsum rows: img rowBase-1 .. rowBase+8 (vr = g-rowBase+1)
#define NQ 66
#define QS 67                  // lo raw layout: quads per row
#define NU 264                 // walk column units: col c = u - 4
#define QA 34                  // de-interleaved half-row stride (quads)
#define HALF 340               // quads per half array (10 rows * 34)
#define PAIR 680               // quads per (A,B) pair
#define RFLT 136               // floats per half-row
#define HFLT 1360              // floats per half array (1360 % 32 == 16 -> A/B banks disjoint)

// reciprocal of valid-count for avgpool (count_include_pad=False); 0 outside image
__device__ __forceinline__ float rcnt0(int i, int p) {
    if (i < 0 || i > Hc - 1) return 0.f;
    int lo = i - p; if (lo < 0) lo = 0;
    int hi = i + p; if (hi > Hc - 1) hi = Hc - 1;
    return __fdividef(1.f, (float)(hi - lo + 1));
}

__device__ __forceinline__ float bn_silu(float acc, float scal, float shft) {
    float v = fmaf(acc, scal, shft);
    return v * __fdividef(1.f, 1.f + __expf(-v));
}

// 3 consecutive quads -> 12 floats (lo path, interleaved layout)
__device__ __forceinline__ void ld12(const float4* __restrict__ p, float* __restrict__ d) {
    float4 A = p[0], B = p[1], C = p[2];
    d[0]=A.x; d[1]=A.y; d[2]=A.z;  d[3]=A.w;
    d[4]=B.x; d[5]=B.y; d[6]=B.z;  d[7]=B.w;
    d[8]=C.x; d[9]=C.y; d[10]=C.z; d[11]=C.w;
}

// quads 2J..2J+3 (cols 8J-4..8J+11) from a de-interleaved pair, row `row`
__device__ __forceinline__ void ld16p(const float4* __restrict__ pairp, int row, int J,
                                      float* __restrict__ d) {
    float4 A0 = pairp[row * QA + J];
    float4 B0 = pairp[HALF + row * QA + J];
    float4 A1 = pairp[row * QA + J + 1];
    float4 B1 = pairp[HALF + row * QA + J + 1];
    d[0]=A0.x; d[1]=A0.y; d[2]=A0.z;  d[3]=A0.w;
    d[4]=B0.x; d[5]=B0.y; d[6]=B0.z;  d[7]=B0.w;
    d[8]=A1.x; d[9]=A1.y; d[10]=A1.z; d[11]=A1.w;
    d[12]=B1.x; d[13]=B1.y; d[14]=B1.z; d[15]=B1.w;
}

// 3x3 conv, 8-wide x 2 rows, over pair-layout buffer rows s0..s0+3.
// Output col 8J+p needs buffer cols 8J+p-1..8J+p+1 -> u[p+kc+3].
__device__ __forceinline__ void conv3_scatter8(const float4* __restrict__ pairp, int s0, int J,
                                               const float* __restrict__ sw,
                                               float inv, float shft,
                                               float* __restrict__ outp, int gy0) {
    float w[9];
#pragma unroll
    for (int i = 0; i < 9; i++) w[i] = sw[i];
    float a0[8] = {0,0,0,0,0,0,0,0}, a1[8] = {0,0,0,0,0,0,0,0};
#pragma unroll
    for (int r = 0; r < 4; r++) {
        float u[16];
        ld16p(pairp, s0 + r, J, u);
        if (r < 3) {
#pragma unroll
            for (int kc = 0; kc < 3; kc++) {
                float wv = w[r * 3 + kc];
#pragma unroll
                for (int p = 0; p < 8; p++) a0[p] = fmaf(wv, u[p + kc + 3], a0[p]);
            }
        }
        if (r >= 1) {
#pragma unroll
            for (int kc = 0; kc < 3; kc++) {
                float wv = w[(r - 1) * 3 + kc];
#pragma unroll
                for (int p = 0; p < 8; p++) a1[p] = fmaf(wv, u[p + kc + 3], a1[p]);
            }
        }
    }
    float4 o;
    o.x = bn_silu(a0[0], inv, shft); o.y = bn_silu(a0[1], inv, shft);
    o.z = bn_silu(a0[2], inv, shft); o.w = bn_silu(a0[3], inv, shft);
    *(float4*)(outp + (size_t)gy0 * Wc) = o;
    o.x = bn_silu(a0[4], inv, shft); o.y = bn_silu(a0[5], inv, shft);
    o.z = bn_silu(a0[6], inv, shft); o.w = bn_silu(a0[7], inv, shft);
    *(float4*)(outp + (size_t)gy0 * Wc + 4) = o;
    o.x = bn_silu(a1[0], inv, shft); o.y = bn_silu(a1[1], inv, shft);
    o.z = bn_silu(a1[2], inv, shft); o.w = bn_silu(a1[3], inv, shft);
    *(float4*)(outp + (size_t)(gy0 + 1) * Wc) = o;
    o.x = bn_silu(a1[4], inv, shft); o.y = bn_silu(a1[5], inv, shft);
    o.z = bn_silu(a1[6], inv, shft); o.w = bn_silu(a1[7], inv, shft);
    *(float4*)(outp + (size_t)(gy0 + 1) * Wc + 4) = o;
}

__global__ __launch_bounds__(256, 5) void trifreq_kernel(
    const float* __restrict__ x,
    const float* __restrict__ w_lo,
    const float* __restrict__ w_mf,
    const float* __restrict__ w_hf,
    const float* __restrict__ bn_gamma,
    const float* __restrict__ bn_beta,
    const float* __restrict__ bn_mean,
    const float* __restrict__ bn_var,
    float* __restrict__ out)
{
    __shared__ float4 s_buf[2048];   // lo: raw [16][67]; mf: v3|v7|bp pairs; hf: raw|v3|hp pairs
    __shared__ float s_w[25];

    const int t = threadIdx.x;
    const int tileY = blockIdx.x;
    const int ch = blockIdx.y;
    const int b = blockIdx.z;
    const int group = ch >> 5;
    const int k = ch & 31;
    const int rowBase = tileY * TH;

    if (group == 0)      { if (t < 25) s_w[t] = w_lo[k * 25 + t]; }
    else if (group == 1) { if (t < 9)  s_w[t] = w_mf[k * 9 + t]; }
    else                 { if (t < 9)  s_w[t] = w_hf[k * 9 + t]; }

    const float* xp = x + (size_t)(b * Cc + ch) * Hc * Wc;

    // img row for walk slot s is rowBase + s - 4
#define LDR(slot) ((colOK && (unsigned)(rowBase + (slot) - 4) < (unsigned)Hc) \
                   ? colp[(size_t)(rowBase + (slot) - 4) * Wc] : 0.f)

    if (group == 0) {
        // ---- lo load: raw slots 2..13 as float4 quads (interleaved [16][67]) ----
        int rr = 2 + (t >> 4);
        if (rr < 14) {
            int gr = rowBase + rr - 4;
            bool rowOK = (unsigned)gr < (unsigned)Hc;
            const float* rowp = xp + gr * Wc;
            float4* srow = s_buf + rr * QS;
            for (int qq = (t & 15); qq < NQ; qq += 16) {
                float4 v = make_float4(0.f, 0.f, 0.f, 0.f);
                if (qq >= 1 && qq <= 64 && rowOK)
                    v = *(const float4*)(rowp + (qq - 1) * 4);
                srow[qq] = v;
            }
        }
    } else if (group == 1) {
        // ---- mf walk: column units, fused v3/v7 into pair layout ----
        float* v3f = (float*)s_buf;
        float* v7f = (float*)(s_buf + PAIR);
        for (int u = t; u < NU; u += 256) {
            int c = u - 4;
            bool colOK = (unsigned)c < (unsigned)Wc;
            const float* colp = xp + c;
            int quad = u >> 2;
            int cb = (quad & 1) * HFLT + ((quad >> 1) << 2) + (u & 3);
            float r[7];
#pragma unroll
            for (int s = 0; s < 7; s++) r[s] = LDR(s);
            float s3 = r[2] + r[3] + r[4];
            float s7 = r[0]+r[1]+r[2]+r[3]+r[4]+r[5]+r[6];
            v3f[cb] = s3; v7f[cb] = s7;
#pragma unroll
            for (int vr = 1; vr <= 9; vr++) {
                float newv = LDR(vr + 6);
                s3 += r[(vr + 4) % 7] - r[(vr + 1) % 7];
                s7 += newv - r[(vr - 1) % 7];
                r[(vr - 1) % 7] = newv;
                v3f[cb + vr * RFLT] = s3;
                v7f[cb + vr * RFLT] = s7;
            }
        }
    } else {
        // ---- hf walk: column units, raw rows 0..9 (img rowBase-1..+8) + fused v3 ----
        float* rawf = (float*)s_buf;
        float* v3f = (float*)(s_buf + PAIR);
        for (int u = t; u < NU; u += 256) {
            int c = u - 4;
            bool colOK = (unsigned)c < (unsigned)Wc;
            const float* colp = xp + c;
            int quad = u >> 2;
            int cb = (quad & 1) * HFLT + ((quad >> 1) << 2) + (u & 3);
            float a = LDR(2), bb = LDR(3), cc;
            rawf[cb] = bb;                              // raw row 0 = img rowBase-1
#pragma unroll
            for (int vr = 0; vr <= 9; vr++) {
                cc = LDR(vr + 4);                       // img row rowBase+vr
                if (vr <= 8) rawf[cb + (vr + 1) * RFLT] = cc;
                v3f[cb + vr * RFLT] = a + bb + cc;      // centered img row rowBase+vr-1
                a = bb; bb = cc;
            }
        }
    }
    // zero conv-buffer halo quads (quad 0 = A[.][0], quad 65 = B[.][32]) for mf/hf
    if (group != 0 && t < 2 * VRS) {
        float4 z = make_float4(0.f, 0.f, 0.f, 0.f);
        int r = t % VRS;
        if (t < VRS) s_buf[2 * PAIR + r * QA] = z;
        else         s_buf[2 * PAIR + HALF + r * QA + 32] = z;
    }
    __syncthreads();

    const int oc = 3 * k + group;                 // channel shuffle folded in
    const float inv  = bn_gamma[oc] * rsqrtf(bn_var[oc] + 1e-5f);
    const float shft = bn_beta[oc] - bn_mean[oc] * inv;

    if (group == 0) {
        // ===== lo: 5x5 dwconv, 4-wide scatter over 6 raw rows (proven R11 path) =====
        const int j = t & 63;
        const int rc = t >> 6;
        const int gy0 = rowBase + 2 * rc;
        float* outp = out + (size_t)(b * Cc + oc) * Hc * Wc + j * 4;
        float w[25];
#pragma unroll
        for (int i = 0; i < 25; i++) w[i] = s_w[i];
        float a0[4] = {0.f,0.f,0.f,0.f}, a1[4] = {0.f,0.f,0.f,0.f};
#pragma unroll
        for (int rrow = 0; rrow < 6; rrow++) {
            float u[12];
            ld12(s_buf + (2 * rc + 2 + rrow) * QS + j, u);   // img row gy0-2+rrow
            if (rrow < 5) {
#pragma unroll
                for (int kc = 0; kc < 5; kc++) {
                    float wv = w[rrow * 5 + kc];
#pragma unroll
                    for (int p = 0; p < 4; p++) a0[p] = fmaf(wv, u[p + kc + 2], a0[p]);
                }
            }
            if (rrow >= 1) {
#pragma unroll
                for (int kc = 0; kc < 5; kc++) {
                    float wv = w[(rrow - 1) * 5 + kc];
#pragma unroll
                    for (int p = 0; p < 4; p++) a1[p] = fmaf(wv, u[p + kc + 2], a1[p]);
                }
            }
        }
        float4 o;
        o.x = bn_silu(a0[0], inv, shft); o.y = bn_silu(a0[1], inv, shft);
        o.z = bn_silu(a0[2], inv, shft); o.w = bn_silu(a0[3], inv, shft);
        *(float4*)(outp + (size_t)gy0 * Wc) = o;
        o.x = bn_silu(a1[0], inv, shft); o.y = bn_silu(a1[1], inv, shft);
        o.z = bn_silu(a1[2], inv, shft); o.w = bn_silu(a1[3], inv, shft);
        *(float4*)(outp + (size_t)(gy0 + 1) * Wc) = o;
        return;
    }

    const int J = t & 31;          // 8-col segment: cols 8J..8J+7
    const int slotW = t >> 5;      // warp id: bp/hp row slot

    if (group == 1) {
        // ===== mf: band-pass once, 8-wide, into bp pair =====
        const float4* v3p = s_buf;
        const float4* v7p = s_buf + PAIR;
        float4* bpp = s_buf + 2 * PAIR;
        float icx7[8];
#pragma unroll
        for (int m = 0; m < 8; m++) {
            int c = 8 * J + m;
            int cnt = (c < 3 ? c : 3) + (255 - c < 3 ? 255 - c : 3) + 1;
            icx7[m] = __fdividef(1.f, (float)cnt);
        }
        for (int vr = slotW; vr < VRS; vr += 8) {
            int g = rowBase + vr - 1;
            float iy3 = rcnt0(g, 1), iy7 = rcnt0(g, 3);
            float u3[16], u7[16], bp[8];
            ld16p(v3p, vr, J, u3);
            float h3 = u3[3] + u3[4] + u3[5];        // col 8J
#pragma unroll
            for (int m = 0; m < 8; m++) {
                int c = 8 * J + m;
                float ic3 = (c == 0 || c == 255) ? 0.5f : (1.f / 3.f);
                bp[m] = h3 * (ic3 * iy3);
                if (m < 7) h3 += u3[m + 6] - u3[m + 3];
            }
            ld16p(v7p, vr, J, u7);
            float h7 = u7[1]+u7[2]+u7[3]+u7[4]+u7[5]+u7[6]+u7[7];   // col 8J
#pragma unroll
            for (int m = 0; m < 8; m++) {
                bp[m] -= h7 * (icx7[m] * iy7);
                if (m < 7) h7 += u7[m + 8] - u7[m + 1];
            }
            float4 o;
            o.x = bp[0]; o.y = bp[1]; o.z = bp[2]; o.w = bp[3];
            bpp[HALF + vr * QA + J] = o;             // quad 2J+1
            o.x = bp[4]; o.y = bp[5]; o.z = bp[6]; o.w = bp[7];
            bpp[vr * QA + J + 1] = o;                // quad 2J+2
        }
        __syncthreads();
        if (t < 128) {
            const int band = t >> 5;
            float* outp = out + (size_t)(b * Cc + oc) * Hc * Wc + J * 8;
            conv3_scatter8(bpp, 2 * band, J, s_w, inv, shft, outp, rowBase + 2 * band);
        }
        return;
    }

    // ===== hf: high-pass once, 8-wide, into hp pair =====
    {
        const float4* rawp = s_buf;
        const float4* v3p = s_buf + PAIR;
        float4* hpp = s_buf + 2 * PAIR;
        for (int vr = slotW; vr < VRS; vr += 8) {
            int g = rowBase + vr - 1;
            float iy3 = rcnt0(g, 1);
            float u3[16], hp[8];
            ld16p(v3p, vr, J, u3);
            float4 R0 = rawp[HALF + vr * QA + J];        // raw cols 8J..8J+3
            float4 R1 = rawp[vr * QA + J + 1];           // raw cols 8J+4..8J+7
            float ur[8] = {R0.x, R0.y, R0.z, R0.w, R1.x, R1.y, R1.z, R1.w};
            float h3 = u3[3] + u3[4] + u3[5];            // col 8J
#pragma unroll
            for (int m = 0; m < 8; m++) {
                int c = 8 * J + m;
                float ic3 = (c == 0 || c == 255) ? 0.5f : (1.f / 3.f);
                hp[m] = ur[m] - h3 * (ic3 * iy3);
                if (m < 7) h3 += u3[m + 6] - u3[m + 3];
            }
            float4 o;
            o.x = hp[0]; o.y = hp[1]; o.z = hp[2]; o.w = hp[3];
            hpp[HALF + vr * QA + J] = o;
            o.x = hp[4]; o.y = hp[5]; o.z = hp[6]; o.w = hp[7];
            hpp[vr * QA + J + 1] = o;
        }
        __syncthreads();
        if (t < 128) {
            const int band = t >> 5;
            float* outp = out + (size_t)(b * Cc + oc) * Hc * Wc + J * 8;
            conv3_scatter8(hpp, 2 * band, J, s_w, inv, shft, outp, rowBase + 2 * band);
        }
    }
}

extern "C" void kernel_launch(void* const* d_in, const int* in_sizes, int n_in,
                              void* d_out, int out_size) {
    (void)in_sizes; (void)n_in; (void)out_size;
    dim3 grid(Hc / TH, Cc, Bc);
    dim3 block(256);
    trifreq_kernel<<<grid, block>>>(
        (const float*)d_in[0], (const float*)d_in[1], (const float*)d_in[2],
        (const float*)d_in[3], (const float*)d_in[4], (const float*)d_in[5],
        (const float*)d_in[6], (const float*)d_in[7], (float*)d_out);
}

// round 13
// speedup vs baseline: 1.3944x; 1.1287x over previous
#include <cuda_runtime.h>

#define Bc 8
#define Cc 96
#define Hc 256
#define Wc 256
#define TH 16
#define VR2 18                 // vsum/bp rows: img rowBase-1 .. rowBase+16 (vr = g-rowBase+1)
#define NU 264                 // walk column units: col c = u - 4
#define RFq 33                 // quads per half-row
#define RFf 132                // floats per half-row
#define HOFq 596               // B-half offset within pair (quads) -> 2384 floats, %32 = 16 banks
#define HOFf 2384
#define PQ 1192                // pair size (quads)

// reciprocal of valid-count for avgpool (count_include_pad=False); 0 outside image
__device__ __forceinline__ float rcnt0(int i, int p) {
    if (i < 0 || i > Hc - 1) return 0.f;
    int lo = i - p; if (lo < 0) lo = 0;
    int hi = i + p; if (hi > Hc - 1) hi = Hc - 1;
    return __fdividef(1.f, (float)(hi - lo + 1));
}

__device__ __forceinline__ float bn_silu(float acc, float scal, float shft) {
    float v = fmaf(acc, scal, shft);
    return v * __fdividef(1.f, 1.f + __expf(-v));
}

// 3 consecutive quads -> 12 floats (lo path, interleaved [20][67] layout)
__device__ __forceinline__ void ld12(const float4* __restrict__ p, float* __restrict__ d) {
    float4 A = p[0], B = p[1], C = p[2];
    d[0]=A.x; d[1]=A.y; d[2]=A.z;  d[3]=A.w;
    d[4]=B.x; d[5]=B.y; d[6]=B.z;  d[7]=B.w;
    d[8]=C.x; d[9]=C.y; d[10]=C.z; d[11]=C.w;
}

// quads 2J..2J+3 (cols 8J-4..8J+11) from a pair at base pq, row `row`
__device__ __forceinline__ void ld16p(const float4* __restrict__ pq, int row, int J,
                                      float* __restrict__ d) {
    const float4* r = pq + row * RFq;
    float4 A0 = r[J];
    float4 B0 = r[HOFq + J];
    float4 A1 = r[J + 1];
    float4 B1 = r[HOFq + J + 1];
    d[0]=A0.x; d[1]=A0.y; d[2]=A0.z;  d[3]=A0.w;
    d[4]=B0.x; d[5]=B0.y; d[6]=B0.z;  d[7]=B0.w;
    d[8]=A1.x; d[9]=A1.y; d[10]=A1.z; d[11]=A1.w;
    d[12]=B1.x; d[13]=B1.y; d[14]=B1.z; d[15]=B1.w;
}

// 3x3 conv, 8-wide x 2 rows, over pair-layout buffer rows s0..s0+3.
__device__ __forceinline__ void conv3_scatter8(const float4* __restrict__ pq, int s0, int J,
                                               const float* __restrict__ sw,
                                               float inv, float shft,
                                               float* __restrict__ outp, int gy0) {
    float w[9];
#pragma unroll
    for (int i = 0; i < 9; i++) w[i] = sw[i];
    float a0[8] = {0,0,0,0,0,0,0,0}, a1[8] = {0,0,0,0,0,0,0,0};
#pragma unroll
    for (int r = 0; r < 4; r++) {
        float u[16];
        ld16p(pq, s0 + r, J, u);
        if (r < 3) {
#pragma unroll
            for (int kc = 0; kc < 3; kc++) {
                float wv = w[r * 3 + kc];
#pragma unroll
                for (int p = 0; p < 8; p++) a0[p] = fmaf(wv, u[p + kc + 3], a0[p]);
            }
        }
        if (r >= 1) {
#pragma unroll
            for (int kc = 0; kc < 3; kc++) {
                float wv = w[(r - 1) * 3 + kc];
#pragma unroll
                for (int p = 0; p < 8; p++) a1[p] = fmaf(wv, u[p + kc + 3], a1[p]);
            }
        }
    }
    float4 o;
    o.x = bn_silu(a0[0], inv, shft); o.y = bn_silu(a0[1], inv, shft);
    o.z = bn_silu(a0[2], inv, shft); o.w = bn_silu(a0[3], inv, shft);
    *(float4*)(outp + (size_t)gy0 * Wc) = o;
    o.x = bn_silu(a0[4], inv, shft); o.y = bn_silu(a0[5], inv, shft);
    o.z = bn_silu(a0[6], inv, shft); o.w = bn_silu(a0[7], inv, shft);
    *(float4*)(outp + (size_t)gy0 * Wc + 4) = o;
    o.x = bn_silu(a1[0], inv, shft); o.y = bn_silu(a1[1], inv, shft);
    o.z = bn_silu(a1[2], inv, shft); o.w = bn_silu(a1[3], inv, shft);
    *(float4*)(outp + (size_t)(gy0 + 1) * Wc) = o;
    o.x = bn_silu(a1[4], inv, shft); o.y = bn_silu(a1[5], inv, shft);
    o.z = bn_silu(a1[6], inv, shft); o.w = bn_silu(a1[7], inv, shft);
    *(float4*)(outp + (size_t)(gy0 + 1) * Wc + 4) = o;
}

__global__ __launch_bounds__(256, 5) void trifreq_kernel(
    const float* __restrict__ x,
    const float* __restrict__ w_lo,
    const float* __restrict__ w_mf,
    const float* __restrict__ w_hf,
    const float* __restrict__ bn_gamma,
    const float* __restrict__ bn_beta,
    const float* __restrict__ bn_mean,
    const float* __restrict__ bn_var,
    float* __restrict__ out)
{
    __shared__ float4 s_buf[2 * PQ];   // lo: raw [20][67]; mf: v3|v7 pairs (bp in-place in v3);
                                       // hf: raw|v3 pairs (hp in-place in v3)
    __shared__ float s_w[25];

    const int t = threadIdx.x;
    const int tileY = blockIdx.x;
    const int ch = blockIdx.y;
    const int b = blockIdx.z;
    const int group = ch >> 5;
    const int k = ch & 31;
    const int rowBase = tileY * TH;

    if (group == 0)      { if (t < 25) s_w[t] = w_lo[k * 25 + t]; }
    else if (group == 1) { if (t < 9)  s_w[t] = w_mf[k * 9 + t]; }
    else                 { if (t < 9)  s_w[t] = w_hf[k * 9 + t]; }

    const float* xp = x + (size_t)(b * Cc + ch) * Hc * Wc;

    // img row for walk slot s is rowBase + s - 4
#define LDR(slot) ((colOK && (unsigned)(rowBase + (slot) - 4) < (unsigned)Hc) \
                   ? colp[(size_t)(rowBase + (slot) - 4) * Wc] : 0.f)

    if (group == 0) {
        // ---- lo load: 20 raw rows (img rowBase-2..rowBase+17), interleaved [20][67] ----
        for (int rr = t >> 4; rr < 20; rr += 16) {
            int gr = rowBase + rr - 2;
            bool rowOK = (unsigned)gr < (unsigned)Hc;
            const float* rowp = xp + gr * Wc;
            float4* srow = s_buf + rr * 67;
            for (int qq = (t & 15); qq < 66; qq += 16) {
                float4 v = make_float4(0.f, 0.f, 0.f, 0.f);
                if (qq >= 1 && qq <= 64 && rowOK)
                    v = *(const float4*)(rowp + (qq - 1) * 4);
                srow[qq] = v;
            }
        }
    } else if (group == 1) {
        // ---- mf walk: fused v3/v7 into pairs (v3 pair at 0, v7 pair at PQ) ----
        float* v3f = (float*)s_buf;
        float* v7f = (float*)(s_buf + PQ);
        for (int u = t; u < NU; u += 256) {
            int c = u - 4;
            bool colOK = (unsigned)c < (unsigned)Wc;
            const float* colp = xp + c;
            int quad = u >> 2;
            int cb = (quad & 1) * HOFf + ((quad >> 1) << 2) + (u & 3);
            float r[7];
#pragma unroll
            for (int s = 0; s < 7; s++) r[s] = LDR(s);
            float s3 = r[2] + r[3] + r[4];
            float s7 = r[0]+r[1]+r[2]+r[3]+r[4]+r[5]+r[6];
            v3f[cb] = s3; v7f[cb] = s7;
#pragma unroll
            for (int vr = 1; vr <= 17; vr++) {
                float newv = LDR(vr + 6);
                s3 += r[(vr + 4) % 7] - r[(vr + 1) % 7];
                s7 += newv - r[(vr - 1) % 7];
                r[(vr - 1) % 7] = newv;
                v3f[cb + vr * RFf] = s3;
                v7f[cb + vr * RFf] = s7;
            }
        }
    } else {
        // ---- hf walk: raw pair (rows img rowBase-1..+16) at 0, fused v3 pair at PQ ----
        float* rawf = (float*)s_buf;
        float* v3f = (float*)(s_buf + PQ);
        for (int u = t; u < NU; u += 256) {
            int c = u - 4;
            bool colOK = (unsigned)c < (unsigned)Wc;
            const float* colp = xp + c;
            int quad = u >> 2;
            int cb = (quad & 1) * HOFf + ((quad >> 1) << 2) + (u & 3);
            float a = LDR(2), bb = LDR(3), cc;
            rawf[cb] = bb;                          // raw row 0 = img rowBase-1
#pragma unroll
            for (int vr = 0; vr <= 17; vr++) {
                cc = LDR(vr + 4);                   // img row rowBase+vr
                if (vr <= 16) rawf[cb + (vr + 1) * RFf] = cc;   // raw rows 1..17
                v3f[cb + vr * RFf] = a + bb + cc;   // centered img rowBase+vr-1
                a = bb; bb = cc;
            }
        }
    }
    __syncthreads();

    const int oc = 3 * k + group;                 // channel shuffle folded in
    const float inv  = bn_gamma[oc] * rsqrtf(bn_var[oc] + 1e-5f);
    const float shft = bn_beta[oc] - bn_mean[oc] * inv;

    if (group == 0) {
        // ===== lo: 5x5 dwconv, 4-wide scatter, two 2-row bands per thread =====
        const int j = t & 63;
        const int rc = t >> 6;
        float* outp = out + (size_t)(b * Cc + oc) * Hc * Wc + j * 4;
        float w[25];
#pragma unroll
        for (int i = 0; i < 25; i++) w[i] = s_w[i];
#pragma unroll
        for (int bb2 = 0; bb2 < 2; bb2++) {
            const int band = rc + bb2 * 4;
            const int gy0 = rowBase + 2 * band;
            float a0[4] = {0.f,0.f,0.f,0.f}, a1[4] = {0.f,0.f,0.f,0.f};
#pragma unroll
            for (int rrow = 0; rrow < 6; rrow++) {
                float u[12];
                ld12(s_buf + (2 * band + rrow) * 67 + j, u);   // img row gy0-2+rrow
                if (rrow < 5) {
#pragma unroll
                    for (int kc = 0; kc < 5; kc++) {
                        float wv = w[rrow * 5 + kc];
#pragma unroll
                        for (int p = 0; p < 4; p++) a0[p] = fmaf(wv, u[p + kc + 2], a0[p]);
                    }
                }
                if (rrow >= 1) {
#pragma unroll
                    for (int kc = 0; kc < 5; kc++) {
                        float wv = w[(rrow - 1) * 5 + kc];
#pragma unroll
                        for (int p = 0; p < 4; p++) a1[p] = fmaf(wv, u[p + kc + 2], a1[p]);
                    }
                }
            }
            float4 o;
            o.x = bn_silu(a0[0], inv, shft); o.y = bn_silu(a0[1], inv, shft);
            o.z = bn_silu(a0[2], inv, shft); o.w = bn_silu(a0[3], inv, shft);
            *(float4*)(outp + (size_t)gy0 * Wc) = o;
            o.x = bn_silu(a1[0], inv, shft); o.y = bn_silu(a1[1], inv, shft);
            o.z = bn_silu(a1[2], inv, shft); o.w = bn_silu(a1[3], inv, shft);
            *(float4*)(outp + (size_t)(gy0 + 1) * Wc) = o;
        }
        return;
    }

    const int J = t & 31;          // 8-col segment: cols 8J..8J+7
    const int warpid = t >> 5;

    if (group == 1) {
        // ===== mf: band-pass once, 8-wide, in-place over v3 pair =====
        float icx7[8];
#pragma unroll
        for (int m = 0; m < 8; m++) {
            int c = 8 * J + m;
            int cnt = (c < 3 ? c : 3) + (255 - c < 3 ? 255 - c : 3) + 1;
            icx7[m] = __fdividef(1.f, (float)cnt);
        }
        for (int vr = warpid; vr < VR2; vr += 8) {
            int g = rowBase + vr - 1;
            float iy3 = rcnt0(g, 1), iy7 = rcnt0(g, 3);
            float u3[16], u7[16], bp[8];
            ld16p(s_buf, vr, J, u3);
            ld16p(s_buf + PQ, vr, J, u7);
            float h3 = u3[3] + u3[4] + u3[5];        // col 8J
#pragma unroll
            for (int m = 0; m < 8; m++) {
                int c = 8 * J + m;
                float ic3 = (c == 0 || c == 255) ? 0.5f : (1.f / 3.f);
                bp[m] = h3 * (ic3 * iy3);
                if (m < 7) h3 += u3[m + 6] - u3[m + 3];
            }
            float h7 = u7[1]+u7[2]+u7[3]+u7[4]+u7[5]+u7[6]+u7[7];   // col 8J
#pragma unroll
            for (int m = 0; m < 8; m++) {
                bp[m] -= h7 * (icx7[m] * iy7);
                if (m < 7) h7 += u7[m + 8] - u7[m + 1];
            }
            __syncwarp();                            // all reads of this row done before overwrite
            float4 o;
            o.x = bp[0]; o.y = bp[1]; o.z = bp[2]; o.w = bp[3];
            s_buf[HOFq + vr * RFq + J] = o;          // quad 2J+1 (cols 8J..8J+3)
            o.x = bp[4]; o.y = bp[5]; o.z = bp[6]; o.w = bp[7];
            s_buf[vr * RFq + J + 1] = o;             // quad 2J+2 (cols 8J+4..8J+7)
        }
        __syncthreads();
        {
            const int band = warpid;                 // 0..7, all 256 threads active
            float* outp = out + (size_t)(b * Cc + oc) * Hc * Wc + J * 8;
            conv3_scatter8(s_buf, 2 * band, J, s_w, inv, shft, outp, rowBase + 2 * band);
        }
        return;
    }

    // ===== hf: high-pass once, 8-wide, in-place over v3 pair =====
    {
        for (int vr = warpid; vr < VR2; vr += 8) {
            int g = rowBase + vr - 1;
            float iy3 = rcnt0(g, 1);
            float u3[16], hp[8];
            ld16p(s_buf + PQ, vr, J, u3);
            float4 R0 = s_buf[HOFq + vr * RFq + J];      // raw cols 8J..8J+3
            float4 R1 = s_buf[vr * RFq + J + 1];         // raw cols 8J+4..8J+7
            float ur[8] = {R0.x, R0.y, R0.z, R0.w, R1.x, R1.y, R1.z, R1.w};
            float h3 = u3[3] + u3[4] + u3[5];            // col 8J
#pragma unroll
            for (int m = 0; m < 8; m++) {
                int c = 8 * J + m;
                float ic3 = (c == 0 || c == 255) ? 0.5f : (1.f / 3.f);
                hp[m] = ur[m] - h3 * (ic3 * iy3);
                if (m < 7) h3 += u3[m + 6] - u3[m + 3];
            }
            __syncwarp();
            float4 o;
            o.x = hp[0]; o.y = hp[1]; o.z = hp[2]; o.w = hp[3];
            s_buf[PQ + HOFq + vr * RFq + J] = o;
            o.x = hp[4]; o.y = hp[5]; o.z = hp[6]; o.w = hp[7];
            s_buf[PQ + vr * RFq + J + 1] = o;
        }
        __syncthreads();
        {
            const int band = warpid;
            float* outp = out + (size_t)(b * Cc + oc) * Hc * Wc + J * 8;
            conv3_scatter8(s_buf + PQ, 2 * band, J, s_w, inv, shft, outp, rowBase + 2 * band);
        }
    }
}

extern "C" void kernel_launch(void* const* d_in, const int* in_sizes, int n_in,
                              void* d_out, int out_size) {
    (void)in_sizes; (void)n_in; (void)out_size;
    dim3 grid(Hc / TH, Cc, Bc);
    dim3 block(256);
    trifreq_kernel<<<grid, block>>>(
        (const float*)d_in[0], (const float*)d_in[1], (const float*)d_in[2],
        (const float*)d_in[3], (const float*)d_in[4], (const float*)d_in[5],
        (const float*)d_in[6], (const float*)d_in[7], (float*)d_out);
}

// round 14
// speedup vs baseline: 1.4256x; 1.0224x over previous
#include <cuda_runtime.h>

#define Bc 8
#define Cc 96
#define Hc 256
#define Wc 256
#define TH 16
#define VR2 18                 // vsum/bp rows: img rowBase-1 .. rowBase+16 (vr = g-rowBase+1)
#define NU 264                 // walk column units: col c = u - 4
#define RFq 33                 // quads per half-row
#define RFf 132                // floats per half-row
#define HOFq 596               // B-half offset within pair (quads) -> 2384 floats, %32 = 16 banks
#define HOFf 2384
#define PQ 1192                // pair size (quads)
#define FULLM 0xffffffffu

// reciprocal of valid-count for avgpool (count_include_pad=False); 0 outside image
__device__ __forceinline__ float rcnt0(int i, int p) {
    if (i < 0 || i > Hc - 1) return 0.f;
    int lo = i - p; if (lo < 0) lo = 0;
    int hi = i + p; if (hi > Hc - 1) hi = Hc - 1;
    return __fdividef(1.f, (float)(hi - lo + 1));
}

__device__ __forceinline__ float bn_silu(float acc, float scal, float shft) {
    float v = fmaf(acc, scal, shft);
    return v * __fdividef(1.f, 1.f + __expf(-v));
}

// 3 consecutive quads -> 12 floats (lo path, interleaved [20][67] layout)
__device__ __forceinline__ void ld12(const float4* __restrict__ p, float* __restrict__ d) {
    float4 A = p[0], B = p[1], C = p[2];
    d[0]=A.x; d[1]=A.y; d[2]=A.z;  d[3]=A.w;
    d[4]=B.x; d[5]=B.y; d[6]=B.z;  d[7]=B.w;
    d[8]=C.x; d[9]=C.y; d[10]=C.z; d[11]=C.w;
}

// quads 2J..2J+3 (cols 8J-4..8J+11) from a pair at base pq, row `row` (full-width read)
__device__ __forceinline__ void ld16p(const float4* __restrict__ pq, int row, int J,
                                      float* __restrict__ d) {
    const float4* r = pq + row * RFq;
    float4 A0 = r[J];
    float4 B0 = r[HOFq + J];
    float4 A1 = r[J + 1];
    float4 B1 = r[HOFq + J + 1];
    d[0]=A0.x; d[1]=A0.y; d[2]=A0.z;  d[3]=A0.w;
    d[4]=B0.x; d[5]=B0.y; d[6]=B0.z;  d[7]=B0.w;
    d[8]=A1.x; d[9]=A1.y; d[10]=A1.z; d[11]=A1.w;
    d[12]=B1.x; d[13]=B1.y; d[14]=B1.z; d[15]=B1.w;
}

// Narrowed 10-col window (cols 8J-1..8J+8) for pair row: 2 LDS.128 + 2 shfl + edge fixups.
// d[i] = col 8J-1+i. All lanes of the warp must execute (converged).
__device__ __forceinline__ void ld10s(const float4* __restrict__ pq, int row, int J,
                                      float* __restrict__ d) {
    const float* pf = (const float*)pq;
    float4 B0 = pq[HOFq + row * RFq + J];       // cols 8J..8J+3
    float4 A1 = pq[row * RFq + J + 1];          // cols 8J+4..8J+7
    float lw = __shfl_up_sync(FULLM, A1.w, 1);  // lane J-1's col 8J-1
    float rw = __shfl_down_sync(FULLM, B0.x, 1);// lane J+1's col 8J+8
    if (J == 0)  lw = pf[row * RFf + 3];            // A[0].w = col -1 (zero halo)
    if (J == 31) rw = pf[HOFf + row * RFf + 128];   // B[32].x = col 256 (zero halo)
    d[0]=lw;
    d[1]=B0.x; d[2]=B0.y; d[3]=B0.z; d[4]=B0.w;
    d[5]=A1.x; d[6]=A1.y; d[7]=A1.z; d[8]=A1.w;
    d[9]=rw;
}

// 3x3 conv, 8-wide x 2 rows, narrowed rows. Output col 8J+p uses c[p..p+2].
__device__ __forceinline__ void conv3_shfl8(const float4* __restrict__ pq, int s0, int J,
                                            const float* __restrict__ sw,
                                            float inv, float shft,
                                            float* __restrict__ outp, int gy0) {
    float w[9];
#pragma unroll
    for (int i = 0; i < 9; i++) w[i] = sw[i];
    float a0[8] = {0,0,0,0,0,0,0,0}, a1[8] = {0,0,0,0,0,0,0,0};
#pragma unroll
    for (int r = 0; r < 4; r++) {
        float c[10];
        ld10s(pq, s0 + r, J, c);
        if (r < 3) {
#pragma unroll
            for (int kc = 0; kc < 3; kc++) {
                float wv = w[r * 3 + kc];
#pragma unroll
                for (int p = 0; p < 8; p++) a0[p] = fmaf(wv, c[p + kc], a0[p]);
            }
        }
        if (r >= 1) {
#pragma unroll
            for (int kc = 0; kc < 3; kc++) {
                float wv = w[(r - 1) * 3 + kc];
#pragma unroll
                for (int p = 0; p < 8; p++) a1[p] = fmaf(wv, c[p + kc], a1[p]);
            }
        }
    }
    float4 o;
    o.x = bn_silu(a0[0], inv, shft); o.y = bn_silu(a0[1], inv, shft);
    o.z = bn_silu(a0[2], inv, shft); o.w = bn_silu(a0[3], inv, shft);
    *(float4*)(outp + (size_t)gy0 * Wc) = o;
    o.x = bn_silu(a0[4], inv, shft); o.y = bn_silu(a0[5], inv, shft);
    o.z = bn_silu(a0[6], inv, shft); o.w = bn_silu(a0[7], inv, shft);
    *(float4*)(outp + (size_t)gy0 * Wc + 4) = o;
    o.x = bn_silu(a1[0], inv, shft); o.y = bn_silu(a1[1], inv, shft);
    o.z = bn_silu(a1[2], inv, shft); o.w = bn_silu(a1[3], inv, shft);
    *(float4*)(outp + (size_t)(gy0 + 1) * Wc) = o;
    o.x = bn_silu(a1[4], inv, shft); o.y = bn_silu(a1[5], inv, shft);
    o.z = bn_silu(a1[6], inv, shft); o.w = bn_silu(a1[7], inv, shft);
    *(float4*)(outp + (size_t)(gy0 + 1) * Wc + 4) = o;
}

__global__ __launch_bounds__(256, 5) void trifreq_kernel(
    const float* __restrict__ x,
    const float* __restrict__ w_lo,
    const float* __restrict__ w_mf,
    const float* __restrict__ w_hf,
    const float* __restrict__ bn_gamma,
    const float* __restrict__ bn_beta,
    const float* __restrict__ bn_mean,
    const float* __restrict__ bn_var,
    float* __restrict__ out)
{
    __shared__ float4 s_buf[2 * PQ];   // lo: raw [20][67]; mf: v3|v7 pairs (bp in-place in v3);
                                       // hf: raw|v3 pairs (hp in-place in v3)
    __shared__ float s_w[25];

    const int t = threadIdx.x;
    const int tileY = blockIdx.x;
    const int ch = blockIdx.y;
    const int b = blockIdx.z;
    const int group = ch >> 5;
    const int k = ch & 31;
    const int rowBase = tileY * TH;

    if (group == 0)      { if (t < 25) s_w[t] = w_lo[k * 25 + t]; }
    else if (group == 1) { if (t < 9)  s_w[t] = w_mf[k * 9 + t]; }
    else                 { if (t < 9)  s_w[t] = w_hf[k * 9 + t]; }

    const float* xp = x + (size_t)(b * Cc + ch) * Hc * Wc;

    // img row for walk slot s is rowBase + s - 4
#define LDR(slot) ((colOK && (unsigned)(rowBase + (slot) - 4) < (unsigned)Hc) \
                   ? colp[(size_t)(rowBase + (slot) - 4) * Wc] : 0.f)

    if (group == 0) {
        // ---- lo load: 20 raw rows (img rowBase-2..rowBase+17), interleaved [20][67] ----
        for (int rr = t >> 4; rr < 20; rr += 16) {
            int gr = rowBase + rr - 2;
            bool rowOK = (unsigned)gr < (unsigned)Hc;
            const float* rowp = xp + gr * Wc;
            float4* srow = s_buf + rr * 67;
            for (int qq = (t & 15); qq < 66; qq += 16) {
                float4 v = make_float4(0.f, 0.f, 0.f, 0.f);
                if (qq >= 1 && qq <= 64 && rowOK)
                    v = *(const float4*)(rowp + (qq - 1) * 4);
                srow[qq] = v;
            }
        }
    } else if (group == 1) {
        // ---- mf walk: preload 24 rows (MLP), then fused v3/v7 into pairs ----
        float* v3f = (float*)s_buf;
        float* v7f = (float*)(s_buf + PQ);
        for (int u = t; u < NU; u += 256) {
            int c = u - 4;
            bool colOK = (unsigned)c < (unsigned)Wc;
            const float* colp = xp + c;
            int quad = u >> 2;
            int cb = (quad & 1) * HOFf + ((quad >> 1) << 2) + (u & 3);
            float rv[24];
#pragma unroll
            for (int s = 0; s < 24; s++) rv[s] = LDR(s);
            float s3 = rv[2] + rv[3] + rv[4];
            float s7 = rv[0]+rv[1]+rv[2]+rv[3]+rv[4]+rv[5]+rv[6];
            v3f[cb] = s3; v7f[cb] = s7;
#pragma unroll
            for (int vr = 1; vr <= 17; vr++) {
                s3 += rv[vr + 4] - rv[vr + 1];
                s7 += rv[vr + 6] - rv[vr - 1];
                v3f[cb + vr * RFf] = s3;
                v7f[cb + vr * RFf] = s7;
            }
        }
    } else {
        // ---- hf walk: preload 20 rows (MLP); raw pair rows 0..17 + v3 pair ----
        float* rawf = (float*)s_buf;
        float* v3f = (float*)(s_buf + PQ);
        for (int u = t; u < NU; u += 256) {
            int c = u - 4;
            bool colOK = (unsigned)c < (unsigned)Wc;
            const float* colp = xp + c;
            int quad = u >> 2;
            int cb = (quad & 1) * HOFf + ((quad >> 1) << 2) + (u & 3);
            float rv[20];
#pragma unroll
            for (int s = 0; s < 20; s++) rv[s] = LDR(s + 2);   // img rowBase-2..+17
#pragma unroll
            for (int r = 0; r < 18; r++) rawf[cb + r * RFf] = rv[r + 1];   // raw row r = img rowBase+r-1
#pragma unroll
            for (int vr = 0; vr < 18; vr++)
                v3f[cb + vr * RFf] = rv[vr] + rv[vr + 1] + rv[vr + 2];     // centered img rowBase+vr-1
        }
    }
    __syncthreads();

    const int oc = 3 * k + group;                 // channel shuffle folded in
    const float inv  = bn_gamma[oc] * rsqrtf(bn_var[oc] + 1e-5f);
    const float shft = bn_beta[oc] - bn_mean[oc] * inv;

    if (group == 0) {
        // ===== lo: 5x5 dwconv, 4-wide scatter, two 2-row bands per thread =====
        const int j = t & 63;
        const int rc = t >> 6;
        float* outp = out + (size_t)(b * Cc + oc) * Hc * Wc + j * 4;
        float w[25];
#pragma unroll
        for (int i = 0; i < 25; i++) w[i] = s_w[i];
#pragma unroll
        for (int bb2 = 0; bb2 < 2; bb2++) {
            const int band = rc + bb2 * 4;
            const int gy0 = rowBase + 2 * band;
            float a0[4] = {0.f,0.f,0.f,0.f}, a1[4] = {0.f,0.f,0.f,0.f};
#pragma unroll
            for (int rrow = 0; rrow < 6; rrow++) {
                float u[12];
                ld12(s_buf + (2 * band + rrow) * 67 + j, u);   // img row gy0-2+rrow
                if (rrow < 5) {
#pragma unroll
                    for (int kc = 0; kc < 5; kc++) {
                        float wv = w[rrow * 5 + kc];
#pragma unroll
                        for (int p = 0; p < 4; p++) a0[p] = fmaf(wv, u[p + kc + 2], a0[p]);
                    }
                }
                if (rrow >= 1) {
#pragma unroll
                    for (int kc = 0; kc < 5; kc++) {
                        float wv = w[(rrow - 1) * 5 + kc];
#pragma unroll
                        for (int p = 0; p < 4; p++) a1[p] = fmaf(wv, u[p + kc + 2], a1[p]);
                    }
                }
            }
            float4 o;
            o.x = bn_silu(a0[0], inv, shft); o.y = bn_silu(a0[1], inv, shft);
            o.z = bn_silu(a0[2], inv, shft); o.w = bn_silu(a0[3], inv, shft);
            *(float4*)(outp + (size_t)gy0 * Wc) = o;
            o.x = bn_silu(a1[0], inv, shft); o.y = bn_silu(a1[1], inv, shft);
            o.z = bn_silu(a1[2], inv, shft); o.w = bn_silu(a1[3], inv, shft);
            *(float4*)(outp + (size_t)(gy0 + 1) * Wc) = o;
        }
        return;
    }

    const int J = t & 31;          // 8-col segment: cols 8J..8J+7
    const int warpid = t >> 5;

    if (group == 1) {
        // ===== mf: band-pass once, 8-wide, in-place over v3 pair =====
        float icx7[8];
#pragma unroll
        for (int m = 0; m < 8; m++) {
            int c = 8 * J + m;
            int cnt = (c < 3 ? c : 3) + (255 - c < 3 ? 255 - c : 3) + 1;
            icx7[m] = __fdividef(1.f, (float)cnt);
        }
        for (int vr = warpid; vr < VR2; vr += 8) {
            int g = rowBase + vr - 1;
            float iy3 = rcnt0(g, 1), iy7 = rcnt0(g, 3);
            float c3[10], u7[16], bp[8];
            ld10s(s_buf, vr, J, c3);               // v3 cols 8J-1..8J+8
            ld16p(s_buf + PQ, vr, J, u7);          // v7 cols 8J-4..8J+11
            float h3 = c3[0] + c3[1] + c3[2];      // col 8J
#pragma unroll
            for (int m = 0; m < 8; m++) {
                int c = 8 * J + m;
                float ic3 = (c == 0 || c == 255) ? 0.5f : (1.f / 3.f);
                bp[m] = h3 * (ic3 * iy3);
                if (m < 7) h3 += c3[m + 3] - c3[m];
            }
            float h7 = u7[1]+u7[2]+u7[3]+u7[4]+u7[5]+u7[6]+u7[7];   // col 8J
#pragma unroll
            for (int m = 0; m < 8; m++) {
                bp[m] -= h7 * (icx7[m] * iy7);
                if (m < 7) h7 += u7[m + 8] - u7[m + 1];
            }
            __syncwarp();                          // row reads complete before overwrite
            float4 o;
            o.x = bp[0]; o.y = bp[1]; o.z = bp[2]; o.w = bp[3];
            s_buf[HOFq + vr * RFq + J] = o;        // B[J] (cols 8J..8J+3)
            o.x = bp[4]; o.y = bp[5]; o.z = bp[6]; o.w = bp[7];
            s_buf[vr * RFq + J + 1] = o;           // A[J+1] (cols 8J+4..8J+7)
        }
        __syncthreads();
        {
            const int band = warpid;
            float* outp = out + (size_t)(b * Cc + oc) * Hc * Wc + J * 8;
            conv3_shfl8(s_buf, 2 * band, J, s_w, inv, shft, outp, rowBase + 2 * band);
        }
        return;
    }

    // ===== hf: high-pass once, 8-wide, in-place over v3 pair =====
    {
        for (int vr = warpid; vr < VR2; vr += 8) {
            int g = rowBase + vr - 1;
            float iy3 = rcnt0(g, 1);
            float c3[10], hp[8];
            ld10s(s_buf + PQ, vr, J, c3);              // v3 cols 8J-1..8J+8
            float4 R0 = s_buf[HOFq + vr * RFq + J];    // raw cols 8J..8J+3
            float4 R1 = s_buf[vr * RFq + J + 1];       // raw cols 8J+4..8J+7
            float ur[8] = {R0.x, R0.y, R0.z, R0.w, R1.x, R1.y, R1.z, R1.w};
            float h3 = c3[0] + c3[1] + c3[2];          // col 8J
#pragma unroll
            for (int m = 0; m < 8; m++) {
                int c = 8 * J + m;
                float ic3 = (c == 0 || c == 255) ? 0.5f : (1.f / 3.f);
                hp[m] = ur[m] - h3 * (ic3 * iy3);
                if (m < 7) h3 += c3[m + 3] - c3[m];
            }
            __syncwarp();
            float4 o;
            o.x = hp[0]; o.y = hp[1]; o.z = hp[2]; o.w = hp[3];
            s_buf[PQ + HOFq + vr * RFq + J] = o;
            o.x = hp[4]; o.y = hp[5]; o.z = hp[6]; o.w = hp[7];
            s_buf[PQ + vr * RFq + J + 1] = o;
        }
        __syncthreads();
        {
            const int band = warpid;
            float* outp = out + (size_t)(b * Cc + oc) * Hc * Wc + J * 8;
            conv3_shfl8(s_buf + PQ, 2 * band, J, s_w, inv, shft, outp, rowBase + 2 * band);
        }
    }
}

extern "C" void kernel_launch(void* const* d_in, const int* in_sizes, int n_in,
                              void* d_out, int out_size) {
    (void)in_sizes; (void)n_in; (void)out_size;
    dim3 grid(Hc / TH, Cc, Bc);
    dim3 block(256);
    trifreq_kernel<<<grid, block>>>(
        (const float*)d_in[0], (const float*)d_in[1], (const float*)d_in[2],
        (const float*)d_in[3], (const float*)d_in[4], (const float*)d_in[5],
        (const float*)d_in[6], (const float*)d_in[7], (float*)d_out);
}